// round 12
// baseline (speedup 1.0000x reference)
#include <cuda_runtime.h>
#include <cuda_bf16.h>
#include <math.h>
#include <float.h>
#include <stdint.h>

#define BB 32
#define NN 1024
#define BN_TOT 32768
#define GXMAX 256

#define SWZ128(o) ((o) ^ (((o) >> 3) & 0x70))

__device__ __forceinline__ uint32_t smem_u32(const void* p) {
    uint32_t a;
    asm("{ .reg .u64 t; cvta.to.shared.u64 t, %1; cvt.u32.u64 %0, t; }"
        : "=r"(a) : "l"(p));
    return a;
}
// fast tanh: t = 1 - 2/(2^(2*log2e*v) + 1); err ~1e-6
__device__ __forceinline__ float tanh_fast(float v) {
    float e;
    asm("ex2.approx.f32 %0, %1;" : "=f"(e) : "f"(v * 2.8853900817779268f));
    float r;
    asm("rcp.approx.f32 %0, %1;" : "=f"(r) : "f"(e + 1.0f));
    return fmaf(-2.0f, r, 1.0f);
}
__device__ __forceinline__ void ldm_x4(uint32_t* r, uint32_t addr) {
    asm volatile("ldmatrix.sync.aligned.m8n8.x4.shared.b16 {%0,%1,%2,%3}, [%4];"
                 : "=r"(r[0]), "=r"(r[1]), "=r"(r[2]), "=r"(r[3]) : "r"(addr));
}
__device__ __forceinline__ void mma16816(float* d, const uint32_t* a, const uint32_t* b) {
    asm volatile(
        "mma.sync.aligned.m16n8k16.row.col.f32.bf16.bf16.f32 "
        "{%0,%1,%2,%3}, {%4,%5,%6,%7}, {%8,%9}, {%0,%1,%2,%3};"
        : "+f"(d[0]), "+f"(d[1]), "+f"(d[2]), "+f"(d[3])
        : "r"(a[0]), "r"(a[1]), "r"(a[2]), "r"(a[3]), "r"(b[0]), "r"(b[1]));
}
__device__ __forceinline__ void cp16(uint32_t dst, const void* src) {
    asm volatile("cp.async.cg.shared.global [%0], [%1], 16;" :: "r"(dst), "l"(src));
}
__device__ __forceinline__ void cp_commit() {
    asm volatile("cp.async.commit_group;" ::: "memory");
}
__device__ __forceinline__ void cp_wait0() {
    asm volatile("cp.async.wait_group 0;" ::: "memory");
}

// ===================== scratch =====================
static constexpr size_t CH = (size_t)BN_TOT;
static constexpr size_t OFF_H1 = 0;
static constexpr size_t OFF_H2 = OFF_H1 + 64 * CH;
static constexpr size_t OFF_H3 = OFF_H2 + 64 * CH;
static constexpr size_t OFF_H4 = OFF_H3 + 64 * CH;
static constexpr size_t OFF_H6 = OFF_H4 + 128 * CH;
static constexpr size_t OFF_H7 = OFF_H6 + 512 * CH;
static constexpr size_t OFF_H8 = OFF_H7 + 256 * CH;
static constexpr size_t OFF_H9 = OFF_H8 + 128 * CH;
static constexpr size_t OFF_MEAN = OFF_H9 + 128 * CH;
static constexpr size_t OFF_RSTD = OFF_MEAN + 10 * 1024;
static constexpr size_t OFF_B6   = OFF_RSTD + 10 * 1024;
static constexpr size_t OFF_CB   = OFF_B6 + (size_t)BB * 512;   // 4096
static constexpr size_t OFF_PS   = OFF_CB + 4096;
static constexpr size_t OFF_PQ   = OFF_PS + 1024 * (size_t)GXMAX;
static constexpr size_t OFF_PM   = OFF_PQ + 1024 * (size_t)GXMAX;
static constexpr size_t TOTAL_F  = OFF_PM + 1024 * (size_t)GXMAX;

__device__ float g_buf[TOTAL_F];

static constexpr size_t WTOT = 1163264;
__device__ __nv_bfloat16 g_whi[WTOT];
__device__ __nv_bfloat16 g_wlo[WTOT];

// ===================== layer table =====================
// kp3 = 3*Cin rounded up to 64. K layout: slot k -> channel k/3, degree k%3
// (features P1, P2, P3; P0==1 folded into cbias).
struct LayerP { int cin, cout, kp3, rows; unsigned woff; unsigned cboff; };
__constant__ LayerP c_L[10] = {
    {  2,   64,   64,  128,       0,    0},
    { 64,   64,  192,  128,    8192,  128},
    { 64,   64,  192,  128,   32768,  256},
    { 64,  128,  192,  128,   57344,  384},
    {128, 1024,  384, 1024,   81920,  512},
    { 64,  512,  192,  512,  475136, 1536},
    {512,  256, 1536,  256,  573440, 2048},
    {256,  128,  768,  128,  966656, 2304},
    {128,  128,  384,  128, 1064960, 2432},
    {128,    3,  384,  128, 1114112, 2560},
};
struct WPtrs { const float* p[10]; };

// ===================== weight convert (all layers, one launch) ==============
__global__ __launch_bounds__(256) void wcvt_all(
    WPtrs wp, __nv_bfloat16* __restrict__ hi, __nv_bfloat16* __restrict__ lo)
{
    const LayerP L = c_L[blockIdx.y];
    int idx = blockIdx.x * 256 + threadIdx.x;
    if (idx >= L.rows * L.kp3) return;
    int r = idx / L.kp3, k = idx - r * L.kp3;
    int ch = k / 3, d = k - ch * 3;
    float w = 0.0f;
    if (r < L.cout && ch < L.cin)
        w = wp.p[blockIdx.y][((size_t)ch * L.cout + r) * 4 + d + 1];
    __nv_bfloat16 h = __float2bfloat16(w);
    hi[L.woff + idx] = h;
    lo[L.woff + idx] = __float2bfloat16(w - __bfloat162float(h));
}

// ===================== constant bias: cb[o] = sum_i W0[i,o] ==========
__global__ __launch_bounds__(256) void cbias_all(WPtrs wp, float* __restrict__ cb)
{
    const LayerP L = c_L[blockIdx.y];
    int r = blockIdx.x * 256 + threadIdx.x;
    if (r >= L.rows) return;
    float s = 0.0f;
    if (r < L.cout) {
        const float* W = wp.p[blockIdx.y];
        for (int i = 0; i < L.cin; i++)
            s += W[((size_t)i * L.cout + r) * 4];
    }
    cb[L.cboff + r] = s;
}

// ===================== fused featurize + split-bf16 HMMA GEMM ==============
// 512 threads = 16 warps (NWM x NWN), warp tile 64x32.
// K-chunk = 64 slots (3 Jacobi features per channel, P0 removed).
template <int NWM, int NWN, int NT>
__global__ __launch_bounds__(512) void kan_mma(
    const float* __restrict__ Hin, const float* __restrict__ mean,
    const float* __restrict__ rstd,
    const __nv_bfloat16* __restrict__ Whi, const __nv_bfloat16* __restrict__ Wlo,
    const float* __restrict__ cb, const float* __restrict__ bbias,
    float* __restrict__ out,
    float* __restrict__ psum, float* __restrict__ pq, float* __restrict__ pmax,
    int Cin, int Cout, int Kp3, int nChunks,
    int writeMode /*0 normal,1 final,2 none*/, int doStats, int doMax,
    int inBatched)
{
    constexpr int M = 64 * NWM;
    constexpr int S_WH = 0;
    constexpr int S_WL = M * 128;
    constexpr int S_FH = 2 * M * 128;
    constexpr int S_FL = 2 * M * 128 + NT * 128;
    constexpr int S_STG = (M + NT) * 256;
    constexpr int NJ = NT / 8;     // points per producer thread

    extern __shared__ __align__(1024) char dsm[];
    const uint32_t sb = smem_u32(dsm);
    const int tid = threadIdx.x;
    const int wid = tid >> 5;
    const int lane = tid & 31;
    const int warpM = wid / NWN;
    const int warpN = wid % NWN;
    const int pBase = blockIdx.x * NT;
    const int oBase = blockIdx.y * M;
    const int bIdx = pBase >> 10;
    const bool hasBN = (mean != nullptr);

    float acc[4][4][4];
#pragma unroll
    for (int mt = 0; mt < 4; mt++)
#pragma unroll
        for (int nt = 0; nt < 4; nt++)
#pragma unroll
            for (int e = 0; e < 4; e++) acc[mt][nt][e] = 0.0f;

    const int slot = tid >> 3;      // producer k-slot (0..63)
    const int sub  = tid & 7;       // point sub-index

    auto stageW = [&](int kc, int sOff) {
#pragma unroll
        for (int l = 0; l < M / 64; l++) {
            int idx = tid + l * 512;
            int row = idx >> 3, c16 = idx & 7;
            size_t g = (size_t)(oBase + row) * Kp3 + (size_t)kc * 64 + c16 * 8;
            uint32_t off = SWZ128(row * 128 + c16 * 16);
            cp16(sb + sOff + S_WH + off, Whi + g);
            cp16(sb + sOff + S_WL + off, Wlo + g);
        }
    };
    auto featStore = [&](int kc, int sOff) {
        const int k = kc * 64 + slot;
        const int ch = k / 3;
        const int d  = k - ch * 3;
        const bool valid = ch < Cin;
        float mn = 0.f, rs = 0.f;
        if (valid) {
            if (hasBN) { rs = rstd[ch]; mn = -mean[ch] * rs; }
            else rs = 1.f;
        }
        const float* hrow;
        if (inBatched)
            hrow = Hin + ((size_t)bIdx * Cin + (valid ? ch : 0)) * NN + (pBase & (NN - 1));
        else
            hrow = Hin + (size_t)(valid ? ch : 0) * BN_TOT + pBase;
        char* fh = dsm + sOff + S_FH;
        char* fl = dsm + sOff + S_FL;
#pragma unroll 8
        for (int j = 0; j < NJ; j++) {
            const int p = sub + 8 * j;
            float xv = valid ? hrow[p] : 0.0f;
            float v = fmaf(xv, rs, valid ? mn : 0.0f);
            float t = tanh_fast(v);
            float q1 = t + t;
            float q2 = fmaf(3.75f * t, t, -0.75f);
            float q3 = t * fmaf(1.8666666666666667f, q2, -1.6f);
            float q = (d == 0) ? q1 : ((d == 1) ? q2 : q3);
            if (!valid) q = 0.0f;
            __nv_bfloat16 h = __float2bfloat16(q);
            __nv_bfloat16 l = __float2bfloat16(q - __bfloat162float(h));
            int o0 = SWZ128(p * 128 + slot * 2);
            *(__nv_bfloat16*)(fh + o0) = h;
            *(__nv_bfloat16*)(fl + o0) = l;
        }
    };
    auto doMMA = [&](int sOff) {
#pragma unroll
        for (int ks = 0; ks < 4; ks++) {
            uint32_t ah[4][4], al[4][4];
#pragma unroll
            for (int mt = 0; mt < 4; mt++) {
                int r = warpM * 64 + mt * 16 + (lane & 15);
                int cB = ks * 32 + (lane >> 4) * 16;
                uint32_t a = sb + sOff + SWZ128(r * 128 + cB);
                ldm_x4(ah[mt], a + S_WH);
                ldm_x4(al[mt], a + S_WL);
            }
#pragma unroll
            for (int ntp = 0; ntp < 2; ntp++) {
                uint32_t fh[4], fl[4];
                int rN = warpN * 32 + ntp * 16 + ((lane >> 4) << 3) + (lane & 7);
                int cB = ks * 32 + ((lane >> 3) & 1) * 16;
                uint32_t a = sb + sOff + SWZ128(rN * 128 + cB);
                ldm_x4(fh, a + S_FH);
                ldm_x4(fl, a + S_FL);
#pragma unroll
                for (int mt = 0; mt < 4; mt++)
#pragma unroll
                    for (int s = 0; s < 2; s++) {
                        int nt = 2 * ntp + s;
                        mma16816(acc[mt][nt], ah[mt], &fh[2 * s]);
                        mma16816(acc[mt][nt], al[mt], &fh[2 * s]);
                        mma16816(acc[mt][nt], ah[mt], &fl[2 * s]);
                    }
            }
        }
    };

    // ---- prologue ----
    stageW(0, 0); cp_commit();
    featStore(0, 0);
    cp_wait0();
    __syncthreads();

    // ---- pipelined main loop ----
    for (int kc = 0; kc < nChunks; kc++) {
        const int sOff = (kc & 1) ? S_STG : 0;
        const int nOff = (kc & 1) ? 0 : S_STG;
        const bool more = (kc + 1 < nChunks);
        if (more) {
            stageW(kc + 1, nOff); cp_commit();
        }
        doMMA(sOff);
        if (more) {
            featStore(kc + 1, nOff);
            cp_wait0();
        }
        __syncthreads();
    }

    // ---- epilogue: constant bias (P0 fold) + optional per-batch bias ----
#pragma unroll
    for (int mt = 0; mt < 4; mt++)
#pragma unroll
        for (int h = 0; h < 2; h++) {
            int o = oBase + warpM * 64 + mt * 16 + h * 8 + (lane >> 2);
            float bv = cb[o];
            if (bbias && o < Cout) bv += bbias[bIdx * Cout + o];
#pragma unroll
            for (int nt = 0; nt < 4; nt++) {
                acc[mt][nt][h * 2 + 0] += bv;
                acc[mt][nt][h * 2 + 1] += bv;
            }
        }

    if (writeMode == 0) {
#pragma unroll
        for (int mt = 0; mt < 4; mt++)
#pragma unroll
            for (int h = 0; h < 2; h++) {
                int o = oBase + warpM * 64 + mt * 16 + h * 8 + (lane >> 2);
                if (o < Cout) {
                    float* rowp = out + (size_t)o * BN_TOT + pBase;
#pragma unroll
                    for (int nt = 0; nt < 4; nt++) {
                        int p = warpN * 32 + nt * 8 + (lane & 3) * 2;
                        *(float2*)(rowp + p) =
                            make_float2(acc[mt][nt][h * 2], acc[mt][nt][h * 2 + 1]);
                    }
                }
            }
    } else if (writeMode == 1) {
#pragma unroll
        for (int mt = 0; mt < 4; mt++)
#pragma unroll
            for (int h = 0; h < 2; h++) {
                int o = oBase + warpM * 64 + mt * 16 + h * 8 + (lane >> 2);
                if (o < 3) {
                    float* rowp = out + ((size_t)bIdx * 3 + o) * NN + (pBase & (NN - 1));
#pragma unroll
                    for (int nt = 0; nt < 4; nt++) {
                        int p = warpN * 32 + nt * 8 + (lane & 3) * 2;
                        rowp[p]     = acc[mt][nt][h * 2];
                        rowp[p + 1] = acc[mt][nt][h * 2 + 1];
                    }
                }
            }
    }

    if (doStats) {
        float* red = (float*)dsm;
#pragma unroll
        for (int mt = 0; mt < 4; mt++)
#pragma unroll
            for (int h = 0; h < 2; h++) {
                float s = 0.f, q = 0.f, mx = -FLT_MAX;
#pragma unroll
                for (int nt = 0; nt < 4; nt++)
#pragma unroll
                    for (int e = 0; e < 2; e++) {
                        float v = acc[mt][nt][h * 2 + e];
                        s += v; q += v * v; mx = fmaxf(mx, v);
                    }
                s += __shfl_xor_sync(~0u, s, 1); s += __shfl_xor_sync(~0u, s, 2);
                q += __shfl_xor_sync(~0u, q, 1); q += __shfl_xor_sync(~0u, q, 2);
                mx = fmaxf(mx, __shfl_xor_sync(~0u, mx, 1));
                mx = fmaxf(mx, __shfl_xor_sync(~0u, mx, 2));
                if ((lane & 3) == 0) {
                    int row = warpM * 64 + mt * 16 + h * 8 + (lane >> 2);
                    red[warpN * M + row] = s;
                    red[NWN * M + warpN * M + row] = q;
                    if (doMax) red[2 * NWN * M + warpN * M + row] = mx;
                }
            }
        __syncthreads();
        if (tid < M) {
            float s = 0.f, q = 0.f, mx = -FLT_MAX;
#pragma unroll
            for (int wn = 0; wn < NWN; wn++) {
                s += red[wn * M + tid];
                q += red[NWN * M + wn * M + tid];
                if (doMax) mx = fmaxf(mx, red[2 * NWN * M + wn * M + tid]);
            }
            int o = oBase + tid;
            psum[(size_t)o * GXMAX + blockIdx.x] = s;
            pq[(size_t)o * GXMAX + blockIdx.x] = q;
            if (doMax) pmax[(size_t)o * GXMAX + blockIdx.x] = mx;
        }
    }
}

// ===================== BN finalize: warp per channel =====================
__global__ __launch_bounds__(256) void bn_fin(
    const float* __restrict__ ps, const float* __restrict__ pq,
    float* __restrict__ mean, float* __restrict__ rstd, int C, int gx)
{
    int w = threadIdx.x >> 5, lane = threadIdx.x & 31;
    int c = blockIdx.x * 8 + w;
    if (c >= C) return;
    float s = 0.f, q = 0.f;
    for (int j = lane; j < gx; j += 32) {
        s += ps[(size_t)c * GXMAX + j];
        q += pq[(size_t)c * GXMAX + j];
    }
#pragma unroll
    for (int o = 16; o; o >>= 1) {
        s += __shfl_xor_sync(~0u, s, o);
        q += __shfl_xor_sync(~0u, q, o);
    }
    if (lane == 0) {
        float m = s * (1.0f / BN_TOT);
        mean[c] = m;
        rstd[c] = rsqrtf(q * (1.0f / BN_TOT) - m * m + 1e-5f);
    }
}

// ============ gf (max over 8 tiles + BN) + bias6 fold (R7 64-block form) ====
__global__ __launch_bounds__(256) void gfbias6(
    const float* __restrict__ pm, const float* __restrict__ mean,
    const float* __restrict__ rstd, const float* __restrict__ W6,
    float* __restrict__ bias6)
{
    const int b = blockIdx.y;
    __shared__ float feat[4096];
    for (int c = threadIdx.x; c < 1024; c += 256) {
        float mx = -FLT_MAX;
#pragma unroll
        for (int j = 0; j < 8; j++)   // L5 uses NT=128 -> 8 tiles per batch
            mx = fmaxf(mx, pm[(size_t)c * GXMAX + b * 8 + j]);
        float g = (mx - mean[c]) * rstd[c];
        float t = tanhf(g);
        float q1 = 2.0f * t;
        float q2 = 3.75f * t * t - 0.75f;
        float q3 = 1.8666666666666667f * t * q2 - 0.8f * q1;
        feat[c * 4 + 0] = 1.0f;
        feat[c * 4 + 1] = q1;
        feat[c * 4 + 2] = q2;
        feat[c * 4 + 3] = q3;
    }
    __syncthreads();
    const int o = blockIdx.x * 256 + threadIdx.x;
    float s = 0.f;
    for (int c = 0; c < 1024; c++) {
        float4 w4 = *(const float4*)(W6 + ((size_t)(64 + c) * 512 + o) * 4);
        s += feat[c * 4 + 0] * w4.x + feat[c * 4 + 1] * w4.y +
             feat[c * 4 + 2] * w4.z + feat[c * 4 + 3] * w4.w;
    }
    bias6[b * 512 + o] = s;
}

// ===================== host =====================
static const LayerP h_L[10] = {
    {  2,   64,   64,  128,       0,    0},
    { 64,   64,  192,  128,    8192,  128},
    { 64,   64,  192,  128,   32768,  256},
    { 64,  128,  192,  128,   57344,  384},
    {128, 1024,  384, 1024,   81920,  512},
    { 64,  512,  192,  512,  475136, 1536},
    {512,  256, 1536,  256,  573440, 2048},
    {256,  128,  768,  128,  966656, 2304},
    {128,  128,  384,  128, 1064960, 2432},
    {128,    3,  384,  128, 1114112, 2560},
};

static constexpr int SMEM_TILE = 196608;

extern "C" void kernel_launch(void* const* d_in, const int* in_sizes, int n_in,
                              void* d_out, int out_size)
{
    (void)in_sizes; (void)n_in; (void)out_size;
    const float* x = (const float*)d_in[0];
    WPtrs wp;
    for (int i = 0; i < 10; i++) wp.p[i] = (const float*)d_in[1 + i];

    float* buf = nullptr;
    cudaGetSymbolAddress((void**)&buf, g_buf);
    __nv_bfloat16* whi = nullptr;
    __nv_bfloat16* wlo = nullptr;
    cudaGetSymbolAddress((void**)&whi, g_whi);
    cudaGetSymbolAddress((void**)&wlo, g_wlo);

    float* h1 = buf + OFF_H1;
    float* h2 = buf + OFF_H2;
    float* h3 = buf + OFF_H3;
    float* h4 = buf + OFF_H4;
    float* h6 = buf + OFF_H6;
    float* h7 = buf + OFF_H7;
    float* h8 = buf + OFF_H8;
    float* h9 = buf + OFF_H9;
    float* meanB = buf + OFF_MEAN;
    float* rstdB = buf + OFF_RSTD;
    float* bias6 = buf + OFF_B6;
    float* cbB   = buf + OFF_CB;
    float* ps    = buf + OFF_PS;
    float* pqb   = buf + OFF_PQ;
    float* pm    = buf + OFF_PM;

    cudaFuncSetAttribute(kan_mma<4, 4, 128>,
                         cudaFuncAttributeMaxDynamicSharedMemorySize, SMEM_TILE);
    cudaFuncSetAttribute(kan_mma<2, 8, 256>,
                         cudaFuncAttributeMaxDynamicSharedMemorySize, SMEM_TILE);

    {
        dim3 g(1536, 10);
        wcvt_all<<<g, 256>>>(wp, whi, wlo);
    }
    {
        dim3 g(4, 10);
        cbias_all<<<g, 256>>>(wp, cbB);
    }

    auto M = [&](int s) { return meanB + s * 1024; };
    auto R = [&](int s) { return rstdB + s * 1024; };

    auto gbig = [&](int l, const float* Hin, const float* mn, const float* rs,
                    const float* bb, float* Hout, int wm, int st, int mx) {
        dim3 grid(BN_TOT / 128, h_L[l].rows / 256, 1);
        kan_mma<4, 4, 128><<<grid, 512, SMEM_TILE>>>(Hin, mn, rs,
            whi + h_L[l].woff, wlo + h_L[l].woff, cbB + h_L[l].cboff, bb,
            Hout, ps, pqb, pm,
            h_L[l].cin, h_L[l].cout, h_L[l].kp3, h_L[l].kp3 / 64, wm, st, mx, 0);
    };
    auto gsm = [&](int l, const float* Hin, const float* mn, const float* rs,
                   const float* bb, float* Hout, int wm, int st, int mx, int ib) {
        dim3 grid(BN_TOT / 256, h_L[l].rows / 128, 1);
        kan_mma<2, 8, 256><<<grid, 512, SMEM_TILE>>>(Hin, mn, rs,
            whi + h_L[l].woff, wlo + h_L[l].woff, cbB + h_L[l].cboff, bb,
            Hout, ps, pqb, pm,
            h_L[l].cin, h_L[l].cout, h_L[l].kp3, h_L[l].kp3 / 64, wm, st, mx, ib);
    };
    auto fin = [&](int slot, int C, int gx) {
        bn_fin<<<(C + 7) / 8, 256>>>(ps, pqb, M(slot), R(slot), C, gx);
    };

    gsm(0, x, nullptr, nullptr, nullptr, h1, 0, 1, 0, 1);   fin(0, 64, 128);
    gsm(1, h1, M(0), R(0), nullptr, h2, 0, 1, 0, 0);        fin(1, 64, 128);
    gsm(2, h2, M(1), R(1), nullptr, h3, 0, 1, 0, 0);        fin(2, 64, 128);
    gsm(3, h3, M(2), R(2), nullptr, h4, 0, 1, 0, 0);        fin(3, 128, 128);
    gbig(4, h4, M(3), R(3), nullptr, nullptr, 2, 1, 1);     fin(4, 1024, 256);

    {
        dim3 g(2, BB);
        gfbias6<<<g, 256>>>(pm, M(4), R(4), wp.p[5], bias6);
    }

    gbig(5, h2, M(1), R(1), bias6, h6, 0, 1, 0);            fin(5, 512, 256);
    gbig(6, h6, M(5), R(5), nullptr, h7, 0, 1, 0);          fin(6, 256, 256);
    gsm(7, h7, M(6), R(6), nullptr, h8, 0, 1, 0, 0);        fin(7, 128, 128);
    gsm(8, h8, M(7), R(7), nullptr, h9, 0, 1, 0, 0);        fin(8, 128, 128);
    gsm(9, h9, M(8), R(8), nullptr, (float*)d_out, 1, 0, 0, 0);
}

// round 13
// speedup vs baseline: 1.1485x; 1.1485x over previous
#include <cuda_runtime.h>
#include <cuda_bf16.h>
#include <math.h>
#include <float.h>
#include <stdint.h>

#define BB 32
#define NN 1024
#define BN_TOT 32768
#define GXMAX 256

#define SWZ128(o) ((o) ^ (((o) >> 3) & 0x70))

__device__ __forceinline__ uint32_t smem_u32(const void* p) {
    uint32_t a;
    asm("{ .reg .u64 t; cvta.to.shared.u64 t, %1; cvt.u32.u64 %0, t; }"
        : "=r"(a) : "l"(p));
    return a;
}
// fast tanh: t = 1 - 2/(2^(2*log2e*v) + 1); err ~1e-6
__device__ __forceinline__ float tanh_fast(float v) {
    float e;
    asm("ex2.approx.f32 %0, %1;" : "=f"(e) : "f"(v * 2.8853900817779268f));
    float r;
    asm("rcp.approx.f32 %0, %1;" : "=f"(r) : "f"(e + 1.0f));
    return fmaf(-2.0f, r, 1.0f);
}
__device__ __forceinline__ void ldm_x4(uint32_t* r, uint32_t addr) {
    asm volatile("ldmatrix.sync.aligned.m8n8.x4.shared.b16 {%0,%1,%2,%3}, [%4];"
                 : "=r"(r[0]), "=r"(r[1]), "=r"(r[2]), "=r"(r[3]) : "r"(addr));
}
__device__ __forceinline__ void mma16816(float* d, const uint32_t* a, const uint32_t* b) {
    asm volatile(
        "mma.sync.aligned.m16n8k16.row.col.f32.bf16.bf16.f32 "
        "{%0,%1,%2,%3}, {%4,%5,%6,%7}, {%8,%9}, {%0,%1,%2,%3};"
        : "+f"(d[0]), "+f"(d[1]), "+f"(d[2]), "+f"(d[3])
        : "r"(a[0]), "r"(a[1]), "r"(a[2]), "r"(a[3]), "r"(b[0]), "r"(b[1]));
}
__device__ __forceinline__ void cp16(uint32_t dst, const void* src) {
    asm volatile("cp.async.cg.shared.global [%0], [%1], 16;" :: "r"(dst), "l"(src));
}
__device__ __forceinline__ void cp_commit() {
    asm volatile("cp.async.commit_group;" ::: "memory");
}
__device__ __forceinline__ void cp_wait0() {
    asm volatile("cp.async.wait_group 0;" ::: "memory");
}

// ===================== scratch =====================
static constexpr size_t CH = (size_t)BN_TOT;
static constexpr size_t OFF_H1 = 0;
static constexpr size_t OFF_H2 = OFF_H1 + 64 * CH;
static constexpr size_t OFF_H3 = OFF_H2 + 64 * CH;
static constexpr size_t OFF_H4 = OFF_H3 + 64 * CH;
static constexpr size_t OFF_H6 = OFF_H4 + 128 * CH;
static constexpr size_t OFF_H7 = OFF_H6 + 512 * CH;
static constexpr size_t OFF_H8 = OFF_H7 + 256 * CH;
static constexpr size_t OFF_H9 = OFF_H8 + 128 * CH;
static constexpr size_t OFF_MEAN = OFF_H9 + 128 * CH;
static constexpr size_t OFF_RSTD = OFF_MEAN + 10 * 1024;
static constexpr size_t OFF_B6   = OFF_RSTD + 10 * 1024;
static constexpr size_t OFF_CB   = OFF_B6 + (size_t)BB * 512;   // 4096
static constexpr size_t OFF_PS   = OFF_CB + 4096;
static constexpr size_t OFF_PQ   = OFF_PS + 1024 * (size_t)GXMAX;
static constexpr size_t OFF_PM   = OFF_PQ + 1024 * (size_t)GXMAX;
static constexpr size_t TOTAL_F  = OFF_PM + 1024 * (size_t)GXMAX;

__device__ float g_buf[TOTAL_F];

static constexpr size_t WTOT = 1163264;
__device__ __nv_bfloat16 g_whi[WTOT];
__device__ __nv_bfloat16 g_wlo[WTOT];

// ===================== layer table =====================
// kp3 = 48 * ceil(Cin/16). Chunk = 48 slots: slot = d*16 + ch_local
// (features P1,P2,P3 of 16 channels; P0==1 folded into cbias).
struct LayerP { int cin, cout, kp3, rows; unsigned woff; unsigned cboff; };
__constant__ LayerP c_L[10] = {
    {  2,   64,   48,  128,       0,    0},
    { 64,   64,  192,  128,    6144,  128},
    { 64,   64,  192,  128,   30720,  256},
    { 64,  128,  192,  128,   55296,  384},
    {128, 1024,  384, 1024,   79872,  512},
    { 64,  512,  192,  512,  473088, 1536},
    {512,  256, 1536,  256,  571392, 2048},
    {256,  128,  768,  128,  964608, 2304},
    {128,  128,  384,  128, 1062912, 2432},
    {128,    3,  384,  128, 1112064, 2560},
};
struct WPtrs { const float* p[10]; };

// ===================== weight convert (all layers, one launch) ==============
__global__ __launch_bounds__(256) void wcvt_all(
    WPtrs wp, __nv_bfloat16* __restrict__ hi, __nv_bfloat16* __restrict__ lo)
{
    const LayerP L = c_L[blockIdx.y];
    int idx = blockIdx.x * 256 + threadIdx.x;
    if (idx >= L.rows * L.kp3) return;
    int r = idx / L.kp3, k = idx - r * L.kp3;
    int kc = k / 48, rem = k - kc * 48;
    int d = rem >> 4, chl = rem & 15;
    int ch = kc * 16 + chl;
    float w = 0.0f;
    if (r < L.cout && ch < L.cin)
        w = wp.p[blockIdx.y][((size_t)ch * L.cout + r) * 4 + d + 1];
    __nv_bfloat16 h = __float2bfloat16(w);
    hi[L.woff + idx] = h;
    lo[L.woff + idx] = __float2bfloat16(w - __bfloat162float(h));
}

// ===================== constant bias: cb[o] = sum_i W0[i,o] ==========
__global__ __launch_bounds__(256) void cbias_all(WPtrs wp, float* __restrict__ cb)
{
    const LayerP L = c_L[blockIdx.y];
    int r = blockIdx.x * 256 + threadIdx.x;
    if (r >= L.rows) return;
    float s = 0.0f;
    if (r < L.cout) {
        const float* W = wp.p[blockIdx.y];
        for (int i = 0; i < L.cin; i++)
            s += W[((size_t)i * L.cout + r) * 4];
    }
    cb[L.cboff + r] = s;
}

// ===================== fused featurize + split-bf16 HMMA GEMM ==============
// 512 threads = 16 warps (NWM x NWN), warp tile 64x32.
// K-chunk = 48 slots (3 k-steps of 16): slot = d*16 + ch_local.
// SMEM rows 128B (first 96 used); 2 stages of (M+NT)*256 bytes.
template <int NWM, int NWN, int NT>
__global__ __launch_bounds__(512) void kan_mma(
    const float* __restrict__ Hin, const float* __restrict__ mean,
    const float* __restrict__ rstd,
    const __nv_bfloat16* __restrict__ Whi, const __nv_bfloat16* __restrict__ Wlo,
    const float* __restrict__ cb, const float* __restrict__ bbias,
    float* __restrict__ out,
    float* __restrict__ psum, float* __restrict__ pq, float* __restrict__ pmax,
    int Cin, int Cout, int Kp3, int nChunks,
    int writeMode /*0 normal,1 final,2 none*/, int doStats, int doMax,
    int inBatched)
{
    constexpr int M = 64 * NWM;
    constexpr int S_WH = 0;
    constexpr int S_WL = M * 128;
    constexpr int S_FH = 2 * M * 128;
    constexpr int S_FL = 2 * M * 128 + NT * 128;
    constexpr int S_STG = (M + NT) * 256;
    constexpr int NJ = NT / 32;     // points per producer thread

    extern __shared__ __align__(1024) char dsm[];
    const uint32_t sb = smem_u32(dsm);
    const int tid = threadIdx.x;
    const int wid = tid >> 5;
    const int lane = tid & 31;
    const int warpM = wid / NWN;
    const int warpN = wid % NWN;
    const int pBase = blockIdx.x * NT;
    const int oBase = blockIdx.y * M;
    const int bIdx = pBase >> 10;
    const bool hasBN = (mean != nullptr);

    float acc[4][4][4];
#pragma unroll
    for (int mt = 0; mt < 4; mt++)
#pragma unroll
        for (int nt = 0; nt < 4; nt++)
#pragma unroll
            for (int e = 0; e < 4; e++) acc[mt][nt][e] = 0.0f;

    const int icl = tid >> 5;       // producer channel (0..15)
    const int pl  = tid & 31;       // producer point sub-index

    auto stageW = [&](int kc, int sOff) {
#pragma unroll
        for (int l = 0; l < (M * 6 + 511) / 512; l++) {
            int idx = tid + l * 512;
            if (idx < M * 6) {
                int row = idx / 6, c16 = idx - row * 6;
                size_t g = (size_t)(oBase + row) * Kp3 + (size_t)kc * 48 + c16 * 8;
                uint32_t off = SWZ128(row * 128 + c16 * 16);
                cp16(sb + sOff + S_WH + off, Whi + g);
                cp16(sb + sOff + S_WL + off, Wlo + g);
            }
        }
    };
    auto featStore = [&](int kc, int sOff) {
        const int ch = kc * 16 + icl;
        const bool valid = ch < Cin;
        float mn = 0.f, rs = 0.f;
        if (valid) {
            if (hasBN) { rs = rstd[ch]; mn = -mean[ch] * rs; }
            else rs = 1.f;
        }
        const float* hrow;
        if (inBatched)
            hrow = Hin + ((size_t)bIdx * Cin + (valid ? ch : 0)) * NN + (pBase & (NN - 1));
        else
            hrow = Hin + (size_t)(valid ? ch : 0) * BN_TOT + pBase;
        char* fh = dsm + sOff + S_FH;
        char* fl = dsm + sOff + S_FL;
#pragma unroll
        for (int j = 0; j < NJ; j++) {
            const int p = pl + 32 * j;
            float xv = valid ? hrow[p] : 0.0f;
            float v = fmaf(xv, rs, mn);
            float t = tanh_fast(v);
            float q1 = t + t;
            float q2 = fmaf(3.75f * t, t, -0.75f);
            float q3 = t * fmaf(1.8666666666666667f, q2, -1.6f);
            // (invalid channels -> weight rows are zero; values don't matter)
            __nv_bfloat16 h1 = __float2bfloat16(q1);
            __nv_bfloat16 h2 = __float2bfloat16(q2);
            __nv_bfloat16 h3 = __float2bfloat16(q3);
            __nv_bfloat16 l1 = __float2bfloat16(q1 - __bfloat162float(h1));
            __nv_bfloat16 l2 = __float2bfloat16(q2 - __bfloat162float(h2));
            __nv_bfloat16 l3 = __float2bfloat16(q3 - __bfloat162float(h3));
            int base = p * 128 + icl * 2;
            int o0 = SWZ128(base);
            int o1 = SWZ128(base + 32);
            int o2 = SWZ128(base + 64);
            *(__nv_bfloat16*)(fh + o0) = h1;
            *(__nv_bfloat16*)(fh + o1) = h2;
            *(__nv_bfloat16*)(fh + o2) = h3;
            *(__nv_bfloat16*)(fl + o0) = l1;
            *(__nv_bfloat16*)(fl + o1) = l2;
            *(__nv_bfloat16*)(fl + o2) = l3;
        }
    };
    auto doMMA = [&](int sOff) {
#pragma unroll
        for (int ks = 0; ks < 3; ks++) {
            uint32_t ah[4][4], al[4][4];
#pragma unroll
            for (int mt = 0; mt < 4; mt++) {
                int r = warpM * 64 + mt * 16 + (lane & 15);
                int cB = ks * 32 + (lane >> 4) * 16;
                uint32_t a = sb + sOff + SWZ128(r * 128 + cB);
                ldm_x4(ah[mt], a + S_WH);
                ldm_x4(al[mt], a + S_WL);
            }
#pragma unroll
            for (int ntp = 0; ntp < 2; ntp++) {
                uint32_t fh[4], fl[4];
                int rN = warpN * 32 + ntp * 16 + ((lane >> 4) << 3) + (lane & 7);
                int cB = ks * 32 + ((lane >> 3) & 1) * 16;
                uint32_t a = sb + sOff + SWZ128(rN * 128 + cB);
                ldm_x4(fh, a + S_FH);
                ldm_x4(fl, a + S_FL);
#pragma unroll
                for (int mt = 0; mt < 4; mt++)
#pragma unroll
                    for (int s = 0; s < 2; s++) {
                        int nt = 2 * ntp + s;
                        mma16816(acc[mt][nt], ah[mt], &fh[2 * s]);
                        mma16816(acc[mt][nt], al[mt], &fh[2 * s]);
                        mma16816(acc[mt][nt], ah[mt], &fl[2 * s]);
                    }
            }
        }
    };

    // ---- prologue ----
    stageW(0, 0); cp_commit();
    featStore(0, 0);
    cp_wait0();
    __syncthreads();

    // ---- pipelined main loop ----
    for (int kc = 0; kc < nChunks; kc++) {
        const int sOff = (kc & 1) ? S_STG : 0;
        const int nOff = (kc & 1) ? 0 : S_STG;
        const bool more = (kc + 1 < nChunks);
        if (more) {
            stageW(kc + 1, nOff); cp_commit();
        }
        doMMA(sOff);
        if (more) {
            featStore(kc + 1, nOff);
            cp_wait0();
        }
        __syncthreads();
    }

    // ---- epilogue: constant bias (P0 fold) + optional per-batch bias ----
#pragma unroll
    for (int mt = 0; mt < 4; mt++)
#pragma unroll
        for (int h = 0; h < 2; h++) {
            int o = oBase + warpM * 64 + mt * 16 + h * 8 + (lane >> 2);
            float bv = cb[o];
            if (bbias && o < Cout) bv += bbias[bIdx * Cout + o];
#pragma unroll
            for (int nt = 0; nt < 4; nt++) {
                acc[mt][nt][h * 2 + 0] += bv;
                acc[mt][nt][h * 2 + 1] += bv;
            }
        }

    if (writeMode == 0) {
#pragma unroll
        for (int mt = 0; mt < 4; mt++)
#pragma unroll
            for (int h = 0; h < 2; h++) {
                int o = oBase + warpM * 64 + mt * 16 + h * 8 + (lane >> 2);
                if (o < Cout) {
                    float* rowp = out + (size_t)o * BN_TOT + pBase;
#pragma unroll
                    for (int nt = 0; nt < 4; nt++) {
                        int p = warpN * 32 + nt * 8 + (lane & 3) * 2;
                        *(float2*)(rowp + p) =
                            make_float2(acc[mt][nt][h * 2], acc[mt][nt][h * 2 + 1]);
                    }
                }
            }
    } else if (writeMode == 1) {
#pragma unroll
        for (int mt = 0; mt < 4; mt++)
#pragma unroll
            for (int h = 0; h < 2; h++) {
                int o = oBase + warpM * 64 + mt * 16 + h * 8 + (lane >> 2);
                if (o < 3) {
                    float* rowp = out + ((size_t)bIdx * 3 + o) * NN + (pBase & (NN - 1));
#pragma unroll
                    for (int nt = 0; nt < 4; nt++) {
                        int p = warpN * 32 + nt * 8 + (lane & 3) * 2;
                        rowp[p]     = acc[mt][nt][h * 2];
                        rowp[p + 1] = acc[mt][nt][h * 2 + 1];
                    }
                }
            }
    }

    if (doStats) {
        float* red = (float*)dsm;
#pragma unroll
        for (int mt = 0; mt < 4; mt++)
#pragma unroll
            for (int h = 0; h < 2; h++) {
                float s = 0.f, q = 0.f, mx = -FLT_MAX;
#pragma unroll
                for (int nt = 0; nt < 4; nt++)
#pragma unroll
                    for (int e = 0; e < 2; e++) {
                        float v = acc[mt][nt][h * 2 + e];
                        s += v; q += v * v; mx = fmaxf(mx, v);
                    }
                s += __shfl_xor_sync(~0u, s, 1); s += __shfl_xor_sync(~0u, s, 2);
                q += __shfl_xor_sync(~0u, q, 1); q += __shfl_xor_sync(~0u, q, 2);
                mx = fmaxf(mx, __shfl_xor_sync(~0u, mx, 1));
                mx = fmaxf(mx, __shfl_xor_sync(~0u, mx, 2));
                if ((lane & 3) == 0) {
                    int row = warpM * 64 + mt * 16 + h * 8 + (lane >> 2);
                    red[warpN * M + row] = s;
                    red[NWN * M + warpN * M + row] = q;
                    if (doMax) red[2 * NWN * M + warpN * M + row] = mx;
                }
            }
        __syncthreads();
        if (tid < M) {
            float s = 0.f, q = 0.f, mx = -FLT_MAX;
#pragma unroll
            for (int wn = 0; wn < NWN; wn++) {
                s += red[wn * M + tid];
                q += red[NWN * M + wn * M + tid];
                if (doMax) mx = fmaxf(mx, red[2 * NWN * M + wn * M + tid]);
            }
            int o = oBase + tid;
            psum[(size_t)o * GXMAX + blockIdx.x] = s;
            pq[(size_t)o * GXMAX + blockIdx.x] = q;
            if (doMax) pmax[(size_t)o * GXMAX + blockIdx.x] = mx;
        }
    }
}

// ===================== BN finalize: warp per channel =====================
__global__ __launch_bounds__(256) void bn_fin(
    const float* __restrict__ ps, const float* __restrict__ pq,
    float* __restrict__ mean, float* __restrict__ rstd, int C, int gx)
{
    int w = threadIdx.x >> 5, lane = threadIdx.x & 31;
    int c = blockIdx.x * 8 + w;
    if (c >= C) return;
    float s = 0.f, q = 0.f;
    for (int j = lane; j < gx; j += 32) {
        s += ps[(size_t)c * GXMAX + j];
        q += pq[(size_t)c * GXMAX + j];
    }
#pragma unroll
    for (int o = 16; o; o >>= 1) {
        s += __shfl_xor_sync(~0u, s, o);
        q += __shfl_xor_sync(~0u, q, o);
    }
    if (lane == 0) {
        float m = s * (1.0f / BN_TOT);
        mean[c] = m;
        rstd[c] = rsqrtf(q * (1.0f / BN_TOT) - m * m + 1e-5f);
    }
}

// ============ gf (max over 8 tiles + BN) + bias6 fold (R7 64-block form) ====
__global__ __launch_bounds__(256) void gfbias6(
    const float* __restrict__ pm, const float* __restrict__ mean,
    const float* __restrict__ rstd, const float* __restrict__ W6,
    float* __restrict__ bias6)
{
    const int b = blockIdx.y;
    __shared__ float feat[4096];
    for (int c = threadIdx.x; c < 1024; c += 256) {
        float mx = -FLT_MAX;
#pragma unroll
        for (int j = 0; j < 8; j++)   // L5 uses NT=128 -> 8 tiles per batch
            mx = fmaxf(mx, pm[(size_t)c * GXMAX + b * 8 + j]);
        float g = (mx - mean[c]) * rstd[c];
        float t = tanhf(g);
        float q1 = 2.0f * t;
        float q2 = 3.75f * t * t - 0.75f;
        float q3 = 1.8666666666666667f * t * q2 - 0.8f * q1;
        feat[c * 4 + 0] = 1.0f;
        feat[c * 4 + 1] = q1;
        feat[c * 4 + 2] = q2;
        feat[c * 4 + 3] = q3;
    }
    __syncthreads();
    const int o = blockIdx.x * 256 + threadIdx.x;
    float s = 0.f;
    for (int c = 0; c < 1024; c++) {
        float4 w4 = *(const float4*)(W6 + ((size_t)(64 + c) * 512 + o) * 4);
        s += feat[c * 4 + 0] * w4.x + feat[c * 4 + 1] * w4.y +
             feat[c * 4 + 2] * w4.z + feat[c * 4 + 3] * w4.w;
    }
    bias6[b * 512 + o] = s;
}

// ===================== host =====================
static const LayerP h_L[10] = {
    {  2,   64,   48,  128,       0,    0},
    { 64,   64,  192,  128,    6144,  128},
    { 64,   64,  192,  128,   30720,  256},
    { 64,  128,  192,  128,   55296,  384},
    {128, 1024,  384, 1024,   79872,  512},
    { 64,  512,  192,  512,  473088, 1536},
    {512,  256, 1536,  256,  571392, 2048},
    {256,  128,  768,  128,  964608, 2304},
    {128,  128,  384,  128, 1062912, 2432},
    {128,    3,  384,  128, 1112064, 2560},
};

static constexpr int SMEM_TILE = 196608;

extern "C" void kernel_launch(void* const* d_in, const int* in_sizes, int n_in,
                              void* d_out, int out_size)
{
    (void)in_sizes; (void)n_in; (void)out_size;
    const float* x = (const float*)d_in[0];
    WPtrs wp;
    for (int i = 0; i < 10; i++) wp.p[i] = (const float*)d_in[1 + i];

    float* buf = nullptr;
    cudaGetSymbolAddress((void**)&buf, g_buf);
    __nv_bfloat16* whi = nullptr;
    __nv_bfloat16* wlo = nullptr;
    cudaGetSymbolAddress((void**)&whi, g_whi);
    cudaGetSymbolAddress((void**)&wlo, g_wlo);

    float* h1 = buf + OFF_H1;
    float* h2 = buf + OFF_H2;
    float* h3 = buf + OFF_H3;
    float* h4 = buf + OFF_H4;
    float* h6 = buf + OFF_H6;
    float* h7 = buf + OFF_H7;
    float* h8 = buf + OFF_H8;
    float* h9 = buf + OFF_H9;
    float* meanB = buf + OFF_MEAN;
    float* rstdB = buf + OFF_RSTD;
    float* bias6 = buf + OFF_B6;
    float* cbB   = buf + OFF_CB;
    float* ps    = buf + OFF_PS;
    float* pqb   = buf + OFF_PQ;
    float* pm    = buf + OFF_PM;

    cudaFuncSetAttribute(kan_mma<4, 4, 128>,
                         cudaFuncAttributeMaxDynamicSharedMemorySize, SMEM_TILE);
    cudaFuncSetAttribute(kan_mma<2, 8, 256>,
                         cudaFuncAttributeMaxDynamicSharedMemorySize, SMEM_TILE);

    {
        dim3 g(1536, 10);
        wcvt_all<<<g, 256>>>(wp, whi, wlo);
    }
    {
        dim3 g(4, 10);
        cbias_all<<<g, 256>>>(wp, cbB);
    }

    auto M = [&](int s) { return meanB + s * 1024; };
    auto R = [&](int s) { return rstdB + s * 1024; };

    auto gbig = [&](int l, const float* Hin, const float* mn, const float* rs,
                    const float* bb, float* Hout, int wm, int st, int mx) {
        dim3 grid(BN_TOT / 128, h_L[l].rows / 256, 1);
        kan_mma<4, 4, 128><<<grid, 512, SMEM_TILE>>>(Hin, mn, rs,
            whi + h_L[l].woff, wlo + h_L[l].woff, cbB + h_L[l].cboff, bb,
            Hout, ps, pqb, pm,
            h_L[l].cin, h_L[l].cout, h_L[l].kp3, h_L[l].kp3 / 48, wm, st, mx, 0);
    };
    auto gsm = [&](int l, const float* Hin, const float* mn, const float* rs,
                   const float* bb, float* Hout, int wm, int st, int mx, int ib) {
        dim3 grid(BN_TOT / 256, h_L[l].rows / 128, 1);
        kan_mma<2, 8, 256><<<grid, 512, SMEM_TILE>>>(Hin, mn, rs,
            whi + h_L[l].woff, wlo + h_L[l].woff, cbB + h_L[l].cboff, bb,
            Hout, ps, pqb, pm,
            h_L[l].cin, h_L[l].cout, h_L[l].kp3, h_L[l].kp3 / 48, wm, st, mx, ib);
    };
    auto fin = [&](int slot, int C, int gx) {
        bn_fin<<<(C + 7) / 8, 256>>>(ps, pqb, M(slot), R(slot), C, gx);
    };

    gsm(0, x, nullptr, nullptr, nullptr, h1, 0, 1, 0, 1);   fin(0, 64, 128);
    gsm(1, h1, M(0), R(0), nullptr, h2, 0, 1, 0, 0);        fin(1, 64, 128);
    gsm(2, h2, M(1), R(1), nullptr, h3, 0, 1, 0, 0);        fin(2, 64, 128);
    gsm(3, h3, M(2), R(2), nullptr, h4, 0, 1, 0, 0);        fin(3, 128, 128);
    gbig(4, h4, M(3), R(3), nullptr, nullptr, 2, 1, 1);     fin(4, 1024, 256);

    {
        dim3 g(2, BB);
        gfbias6<<<g, 256>>>(pm, M(4), R(4), wp.p[5], bias6);
    }

    gbig(5, h2, M(1), R(1), bias6, h6, 0, 1, 0);            fin(5, 512, 256);
    gbig(6, h6, M(5), R(5), nullptr, h7, 0, 1, 0);          fin(6, 256, 256);
    gsm(7, h7, M(6), R(6), nullptr, h8, 0, 1, 0, 0);        fin(7, 128, 128);
    gsm(8, h8, M(7), R(7), nullptr, h9, 0, 1, 0, 0);        fin(8, 128, 128);
    gsm(9, h9, M(8), R(8), nullptr, (float*)d_out, 1, 0, 0, 0);
}

// round 14
// speedup vs baseline: 1.2030x; 1.0475x over previous
#include <cuda_runtime.h>
#include <cuda_bf16.h>
#include <math.h>
#include <float.h>
#include <stdint.h>

#define BB 32
#define NN 1024
#define BN_TOT 32768
#define GXMAX 256

#define SWZ128(o) ((o) ^ (((o) >> 3) & 0x70))

__device__ __forceinline__ uint32_t smem_u32(const void* p) {
    uint32_t a;
    asm("{ .reg .u64 t; cvta.to.shared.u64 t, %1; cvt.u32.u64 %0, t; }"
        : "=r"(a) : "l"(p));
    return a;
}
// fast tanh: t = 1 - 2/(2^(2*log2e*v) + 1); err ~1e-6
__device__ __forceinline__ float tanh_fast(float v) {
    float e;
    asm("ex2.approx.f32 %0, %1;" : "=f"(e) : "f"(v * 2.8853900817779268f));
    float r;
    asm("rcp.approx.f32 %0, %1;" : "=f"(r) : "f"(e + 1.0f));
    return fmaf(-2.0f, r, 1.0f);
}
__device__ __forceinline__ void ldm_x4(uint32_t* r, uint32_t addr) {
    asm volatile("ldmatrix.sync.aligned.m8n8.x4.shared.b16 {%0,%1,%2,%3}, [%4];"
                 : "=r"(r[0]), "=r"(r[1]), "=r"(r[2]), "=r"(r[3]) : "r"(addr));
}
__device__ __forceinline__ void mma16816(float* d, const uint32_t* a, const uint32_t* b) {
    asm volatile(
        "mma.sync.aligned.m16n8k16.row.col.f32.bf16.bf16.f32 "
        "{%0,%1,%2,%3}, {%4,%5,%6,%7}, {%8,%9}, {%0,%1,%2,%3};"
        : "+f"(d[0]), "+f"(d[1]), "+f"(d[2]), "+f"(d[3])
        : "r"(a[0]), "r"(a[1]), "r"(a[2]), "r"(a[3]), "r"(b[0]), "r"(b[1]));
}
__device__ __forceinline__ void cp16(uint32_t dst, const void* src) {
    asm volatile("cp.async.cg.shared.global [%0], [%1], 16;" :: "r"(dst), "l"(src));
}
__device__ __forceinline__ void cp_commit() {
    asm volatile("cp.async.commit_group;" ::: "memory");
}
__device__ __forceinline__ void cp_wait0() {
    asm volatile("cp.async.wait_group 0;" ::: "memory");
}

// ===================== scratch =====================
static constexpr size_t CH = (size_t)BN_TOT;
static constexpr size_t OFF_H1 = 0;
static constexpr size_t OFF_H2 = OFF_H1 + 64 * CH;
static constexpr size_t OFF_H3 = OFF_H2 + 64 * CH;
static constexpr size_t OFF_H4 = OFF_H3 + 64 * CH;
static constexpr size_t OFF_H6 = OFF_H4 + 128 * CH;
static constexpr size_t OFF_H7 = OFF_H6 + 512 * CH;
static constexpr size_t OFF_H8 = OFF_H7 + 256 * CH;
static constexpr size_t OFF_H9 = OFF_H8 + 128 * CH;
static constexpr size_t OFF_MEAN = OFF_H9 + 128 * CH;
static constexpr size_t OFF_RSTD = OFF_MEAN + 10 * 1024;
static constexpr size_t OFF_B6   = OFF_RSTD + 10 * 1024;
static constexpr size_t OFF_CB   = OFF_B6 + (size_t)BB * 512;   // 4096
static constexpr size_t OFF_PS   = OFF_CB + 4096;
static constexpr size_t OFF_PQ   = OFF_PS + 1024 * (size_t)GXMAX;
static constexpr size_t OFF_PM   = OFF_PQ + 1024 * (size_t)GXMAX;
static constexpr size_t TOTAL_F  = OFF_PM + 1024 * (size_t)GXMAX;

__device__ float g_buf[TOTAL_F];

static constexpr size_t WTOT = 1163264;
__device__ __nv_bfloat16 g_whi[WTOT];
__device__ __nv_bfloat16 g_wlo[WTOT];

// ===================== layer table =====================
// kp3 = 48 * ceil(Cin/16). Chunk = 48 slots: slot = d*16 + ch_local
// (features P1,P2,P3 of 16 channels; P0==1 folded into cbias).
struct LayerP { int cin, cout, kp3, rows; unsigned woff; unsigned cboff; };
__constant__ LayerP c_L[10] = {
    {  2,   64,   48,  128,       0,    0},
    { 64,   64,  192,  128,    6144,  128},
    { 64,   64,  192,  128,   30720,  256},
    { 64,  128,  192,  128,   55296,  384},
    {128, 1024,  384, 1024,   79872,  512},
    { 64,  512,  192,  512,  473088, 1536},
    {512,  256, 1536,  256,  571392, 2048},
    {256,  128,  768,  128,  964608, 2304},
    {128,  128,  384,  128, 1062912, 2432},
    {128,    3,  384,  128, 1112064, 2560},
};
struct WPtrs { const float* p[10]; };

// ===================== weight convert (bf16 layers 1..8) ==============
__global__ __launch_bounds__(256) void wcvt_all(
    WPtrs wp, __nv_bfloat16* __restrict__ hi, __nv_bfloat16* __restrict__ lo)
{
    const LayerP L = c_L[blockIdx.y + 1];   // layers 1..8 only
    int idx = blockIdx.x * 256 + threadIdx.x;
    if (idx >= L.rows * L.kp3) return;
    int r = idx / L.kp3, k = idx - r * L.kp3;
    int kc = k / 48, rem = k - kc * 48;
    int d = rem >> 4, chl = rem & 15;
    int ch = kc * 16 + chl;
    float w = 0.0f;
    if (r < L.cout && ch < L.cin)
        w = wp.p[blockIdx.y + 1][((size_t)ch * L.cout + r) * 4 + d + 1];
    __nv_bfloat16 h = __float2bfloat16(w);
    hi[L.woff + idx] = h;
    lo[L.woff + idx] = __float2bfloat16(w - __bfloat162float(h));
}

// ===================== constant bias: cb[o] = sum_i W0[i,o] ==========
__global__ __launch_bounds__(256) void cbias_all(WPtrs wp, float* __restrict__ cb)
{
    const LayerP L = c_L[blockIdx.y + 1];
    int r = blockIdx.x * 256 + threadIdx.x;
    if (r >= L.rows) return;
    float s = 0.0f;
    if (r < L.cout) {
        const float* W = wp.p[blockIdx.y + 1];
        for (int i = 0; i < L.cin; i++)
            s += W[((size_t)i * L.cout + r) * 4];
    }
    cb[L.cboff + r] = s;
}

// ===================== L1 scalar (exact fp32): x(B,2,N) -> h1[64][BN] =======
__global__ __launch_bounds__(256) void layer1_scalar(
    const float* __restrict__ x, const float* __restrict__ w1,
    float* __restrict__ h1)
{
    __shared__ float ws[512];   // (2,64,4)
    for (int i = threadIdx.x; i < 512; i += 256) ws[i] = w1[i];
    __syncthreads();
    const int p = blockIdx.x * 256 + threadIdx.x;   // 0..32767
    const int b = p >> 10, n = p & 1023;
    float feat[2][4];
#pragma unroll
    for (int c = 0; c < 2; c++) {
        float t = tanhf(x[((size_t)b * 2 + c) * NN + n]);
        feat[c][0] = 1.0f;
        feat[c][1] = 2.0f * t;
        feat[c][2] = 3.75f * t * t - 0.75f;
        feat[c][3] = 1.8666666666666667f * t * feat[c][2] - 0.8f * feat[c][1];
    }
#pragma unroll 8
    for (int o = 0; o < 64; o++) {
        float s = 0.0f;
#pragma unroll
        for (int c = 0; c < 2; c++)
#pragma unroll
            for (int d = 0; d < 4; d++)
                s += ws[(c * 64 + o) * 4 + d] * feat[c][d];
        h1[(size_t)o * BN_TOT + p] = s;
    }
}

// ===================== direct BN stats over [C][BN] =====================
__global__ __launch_bounds__(256) void bn_stats_direct(
    const float* __restrict__ H, float* __restrict__ mean,
    float* __restrict__ rstd)
{
    const int c = blockIdx.x;
    const float4* p = (const float4*)(H + (size_t)c * BN_TOT);
    float s = 0.f, q = 0.f;
    for (int i = threadIdx.x; i < BN_TOT / 4; i += 256) {
        float4 v = p[i];
        s += v.x + v.y + v.z + v.w;
        q += v.x * v.x + v.y * v.y + v.z * v.z + v.w * v.w;
    }
    __shared__ float s1[256], s2[256];
    s1[threadIdx.x] = s; s2[threadIdx.x] = q;
    __syncthreads();
    for (int off = 128; off; off >>= 1) {
        if (threadIdx.x < off) {
            s1[threadIdx.x] += s1[threadIdx.x + off];
            s2[threadIdx.x] += s2[threadIdx.x + off];
        }
        __syncthreads();
    }
    if (threadIdx.x == 0) {
        float m = s1[0] * (1.0f / BN_TOT);
        mean[c] = m;
        rstd[c] = rsqrtf(s2[0] * (1.0f / BN_TOT) - m * m + 1e-5f);
    }
}

// ===================== L10 scalar (exact fp32): h9 -> out(B,3,N) ===========
__global__ __launch_bounds__(256) void layer10_scalar(
    const float* __restrict__ h9, const float* __restrict__ mean,
    const float* __restrict__ rstd, const float* __restrict__ w10,
    float* __restrict__ out)
{
    __shared__ float ws[1536];   // (128,3,4)
    __shared__ float sm[128], sr[128];
    for (int i = threadIdx.x; i < 1536; i += 256) ws[i] = w10[i];
    if (threadIdx.x < 128) {
        sm[threadIdx.x] = mean[threadIdx.x];
        sr[threadIdx.x] = rstd[threadIdx.x];
    }
    __syncthreads();
    const int p = blockIdx.x * 256 + threadIdx.x;
    const int b = p >> 10, n = p & 1023;
    float a0 = 0.f, a1 = 0.f, a2 = 0.f;
    for (int i = 0; i < 128; i++) {
        float v = (h9[(size_t)i * BN_TOT + p] - sm[i]) * sr[i];
        float t = tanh_fast(v);
        float q1 = 2.0f * t;
        float q2 = 3.75f * t * t - 0.75f;
        float q3 = 1.8666666666666667f * t * q2 - 0.8f * q1;
        const float* w = ws + i * 12;
        a0 += w[0] + w[1] * q1 + w[2]  * q2 + w[3]  * q3;
        a1 += w[4] + w[5] * q1 + w[6]  * q2 + w[7]  * q3;
        a2 += w[8] + w[9] * q1 + w[10] * q2 + w[11] * q3;
    }
    out[((size_t)b * 3 + 0) * NN + n] = a0;
    out[((size_t)b * 3 + 1) * NN + n] = a1;
    out[((size_t)b * 3 + 2) * NN + n] = a2;
}

// ===================== fused featurize + split-bf16 HMMA GEMM ==============
template <int NWM, int NWN, int NT>
__global__ __launch_bounds__(512) void kan_mma(
    const float* __restrict__ Hin, const float* __restrict__ mean,
    const float* __restrict__ rstd,
    const __nv_bfloat16* __restrict__ Whi, const __nv_bfloat16* __restrict__ Wlo,
    const float* __restrict__ cb, const float* __restrict__ bbias,
    float* __restrict__ out,
    float* __restrict__ psum, float* __restrict__ pq, float* __restrict__ pmax,
    int Cin, int Cout, int Kp3, int nChunks,
    int writeMode /*0 normal,2 none*/, int doStats, int doMax)
{
    constexpr int M = 64 * NWM;
    constexpr int S_WH = 0;
    constexpr int S_WL = M * 128;
    constexpr int S_FH = 2 * M * 128;
    constexpr int S_FL = 2 * M * 128 + NT * 128;
    constexpr int S_STG = (M + NT) * 256;
    constexpr int NJ = NT / 32;

    extern __shared__ __align__(1024) char dsm[];
    const uint32_t sb = smem_u32(dsm);
    const int tid = threadIdx.x;
    const int wid = tid >> 5;
    const int lane = tid & 31;
    const int warpM = wid / NWN;
    const int warpN = wid % NWN;
    const int pBase = blockIdx.x * NT;
    const int oBase = blockIdx.y * M;
    const int bIdx = pBase >> 10;

    float acc[4][4][4];
#pragma unroll
    for (int mt = 0; mt < 4; mt++)
#pragma unroll
        for (int nt = 0; nt < 4; nt++)
#pragma unroll
            for (int e = 0; e < 4; e++) acc[mt][nt][e] = 0.0f;

    const int icl = tid >> 5;
    const int pl  = tid & 31;

    auto stageW = [&](int kc, int sOff) {
#pragma unroll
        for (int l = 0; l < (M * 6 + 511) / 512; l++) {
            int idx = tid + l * 512;
            if (idx < M * 6) {
                int row = idx / 6, c16 = idx - row * 6;
                size_t g = (size_t)(oBase + row) * Kp3 + (size_t)kc * 48 + c16 * 8;
                uint32_t off = SWZ128(row * 128 + c16 * 16);
                cp16(sb + sOff + S_WH + off, Whi + g);
                cp16(sb + sOff + S_WL + off, Wlo + g);
            }
        }
    };
    auto featStore = [&](int kc, int sOff) {
        const int ch = kc * 16 + icl;
        const bool valid = ch < Cin;
        float mn = 0.f, rs = 0.f;
        if (valid) { rs = rstd[ch]; mn = -mean[ch] * rs; }
        const float* hrow = Hin + (size_t)(valid ? ch : 0) * BN_TOT + pBase;
        char* fh = dsm + sOff + S_FH;
        char* fl = dsm + sOff + S_FL;
#pragma unroll
        for (int j = 0; j < NJ; j++) {
            const int p = pl + 32 * j;
            float xv = valid ? hrow[p] : 0.0f;
            float v = fmaf(xv, rs, mn);
            float t = tanh_fast(v);
            float q1 = t + t;
            float q2 = fmaf(3.75f * t, t, -0.75f);
            float q3 = t * fmaf(1.8666666666666667f, q2, -1.6f);
            __nv_bfloat16 h1 = __float2bfloat16(q1);
            __nv_bfloat16 h2 = __float2bfloat16(q2);
            __nv_bfloat16 h3 = __float2bfloat16(q3);
            __nv_bfloat16 l1 = __float2bfloat16(q1 - __bfloat162float(h1));
            __nv_bfloat16 l2 = __float2bfloat16(q2 - __bfloat162float(h2));
            __nv_bfloat16 l3 = __float2bfloat16(q3 - __bfloat162float(h3));
            int base = p * 128 + icl * 2;
            int o0 = SWZ128(base);
            int o1 = SWZ128(base + 32);
            int o2 = SWZ128(base + 64);
            *(__nv_bfloat16*)(fh + o0) = h1;
            *(__nv_bfloat16*)(fh + o1) = h2;
            *(__nv_bfloat16*)(fh + o2) = h3;
            *(__nv_bfloat16*)(fl + o0) = l1;
            *(__nv_bfloat16*)(fl + o1) = l2;
            *(__nv_bfloat16*)(fl + o2) = l3;
        }
    };
    auto doMMA = [&](int sOff) {
#pragma unroll
        for (int ks = 0; ks < 3; ks++) {
            uint32_t ah[4][4], al[4][4];
#pragma unroll
            for (int mt = 0; mt < 4; mt++) {
                int r = warpM * 64 + mt * 16 + (lane & 15);
                int cB = ks * 32 + (lane >> 4) * 16;
                uint32_t a = sb + sOff + SWZ128(r * 128 + cB);
                ldm_x4(ah[mt], a + S_WH);
                ldm_x4(al[mt], a + S_WL);
            }
#pragma unroll
            for (int ntp = 0; ntp < 2; ntp++) {
                uint32_t fh[4], fl[4];
                int rN = warpN * 32 + ntp * 16 + ((lane >> 4) << 3) + (lane & 7);
                int cB = ks * 32 + ((lane >> 3) & 1) * 16;
                uint32_t a = sb + sOff + SWZ128(rN * 128 + cB);
                ldm_x4(fh, a + S_FH);
                ldm_x4(fl, a + S_FL);
#pragma unroll
                for (int mt = 0; mt < 4; mt++)
#pragma unroll
                    for (int s = 0; s < 2; s++) {
                        int nt = 2 * ntp + s;
                        mma16816(acc[mt][nt], ah[mt], &fh[2 * s]);
                        mma16816(acc[mt][nt], al[mt], &fh[2 * s]);
                        mma16816(acc[mt][nt], ah[mt], &fl[2 * s]);
                    }
            }
        }
    };

    // ---- prologue ----
    stageW(0, 0); cp_commit();
    featStore(0, 0);
    cp_wait0();
    __syncthreads();

    // ---- pipelined main loop ----
    for (int kc = 0; kc < nChunks; kc++) {
        const int sOff = (kc & 1) ? S_STG : 0;
        const int nOff = (kc & 1) ? 0 : S_STG;
        const bool more = (kc + 1 < nChunks);
        if (more) {
            stageW(kc + 1, nOff); cp_commit();
        }
        doMMA(sOff);
        if (more) {
            featStore(kc + 1, nOff);
            cp_wait0();
        }
        __syncthreads();
    }

    // ---- epilogue ----
#pragma unroll
    for (int mt = 0; mt < 4; mt++)
#pragma unroll
        for (int h = 0; h < 2; h++) {
            int o = oBase + warpM * 64 + mt * 16 + h * 8 + (lane >> 2);
            float bv = cb[o];
            if (bbias && o < Cout) bv += bbias[bIdx * Cout + o];
#pragma unroll
            for (int nt = 0; nt < 4; nt++) {
                acc[mt][nt][h * 2 + 0] += bv;
                acc[mt][nt][h * 2 + 1] += bv;
            }
        }

    if (writeMode == 0) {
#pragma unroll
        for (int mt = 0; mt < 4; mt++)
#pragma unroll
            for (int h = 0; h < 2; h++) {
                int o = oBase + warpM * 64 + mt * 16 + h * 8 + (lane >> 2);
                if (o < Cout) {
                    float* rowp = out + (size_t)o * BN_TOT + pBase;
#pragma unroll
                    for (int nt = 0; nt < 4; nt++) {
                        int p = warpN * 32 + nt * 8 + (lane & 3) * 2;
                        *(float2*)(rowp + p) =
                            make_float2(acc[mt][nt][h * 2], acc[mt][nt][h * 2 + 1]);
                    }
                }
            }
    }

    if (doStats) {
        float* red = (float*)dsm;
#pragma unroll
        for (int mt = 0; mt < 4; mt++)
#pragma unroll
            for (int h = 0; h < 2; h++) {
                float s = 0.f, q = 0.f, mx = -FLT_MAX;
#pragma unroll
                for (int nt = 0; nt < 4; nt++)
#pragma unroll
                    for (int e = 0; e < 2; e++) {
                        float v = acc[mt][nt][h * 2 + e];
                        s += v; q += v * v; mx = fmaxf(mx, v);
                    }
                s += __shfl_xor_sync(~0u, s, 1); s += __shfl_xor_sync(~0u, s, 2);
                q += __shfl_xor_sync(~0u, q, 1); q += __shfl_xor_sync(~0u, q, 2);
                mx = fmaxf(mx, __shfl_xor_sync(~0u, mx, 1));
                mx = fmaxf(mx, __shfl_xor_sync(~0u, mx, 2));
                if ((lane & 3) == 0) {
                    int row = warpM * 64 + mt * 16 + h * 8 + (lane >> 2);
                    red[warpN * M + row] = s;
                    red[NWN * M + warpN * M + row] = q;
                    if (doMax) red[2 * NWN * M + warpN * M + row] = mx;
                }
            }
        __syncthreads();
        if (tid < M) {
            float s = 0.f, q = 0.f, mx = -FLT_MAX;
#pragma unroll
            for (int wn = 0; wn < NWN; wn++) {
                s += red[wn * M + tid];
                q += red[NWN * M + wn * M + tid];
                if (doMax) mx = fmaxf(mx, red[2 * NWN * M + wn * M + tid]);
            }
            int o = oBase + tid;
            psum[(size_t)o * GXMAX + blockIdx.x] = s;
            pq[(size_t)o * GXMAX + blockIdx.x] = q;
            if (doMax) pmax[(size_t)o * GXMAX + blockIdx.x] = mx;
        }
    }
}

// ===================== BN finalize: warp per channel =====================
__global__ __launch_bounds__(256) void bn_fin(
    const float* __restrict__ ps, const float* __restrict__ pq,
    float* __restrict__ mean, float* __restrict__ rstd, int C, int gx)
{
    int w = threadIdx.x >> 5, lane = threadIdx.x & 31;
    int c = blockIdx.x * 8 + w;
    if (c >= C) return;
    float s = 0.f, q = 0.f;
    for (int j = lane; j < gx; j += 32) {
        s += ps[(size_t)c * GXMAX + j];
        q += pq[(size_t)c * GXMAX + j];
    }
#pragma unroll
    for (int o = 16; o; o >>= 1) {
        s += __shfl_xor_sync(~0u, s, o);
        q += __shfl_xor_sync(~0u, q, o);
    }
    if (lane == 0) {
        float m = s * (1.0f / BN_TOT);
        mean[c] = m;
        rstd[c] = rsqrtf(q * (1.0f / BN_TOT) - m * m + 1e-5f);
    }
}

// ============ gf (max over 8 tiles + BN) + bias6 fold ============
__global__ __launch_bounds__(256) void gfbias6(
    const float* __restrict__ pm, const float* __restrict__ mean,
    const float* __restrict__ rstd, const float* __restrict__ W6,
    float* __restrict__ bias6)
{
    const int b = blockIdx.y;
    __shared__ float feat[4096];
    for (int c = threadIdx.x; c < 1024; c += 256) {
        float mx = -FLT_MAX;
#pragma unroll
        for (int j = 0; j < 8; j++)   // L5 uses NT=128 -> 8 tiles per batch
            mx = fmaxf(mx, pm[(size_t)c * GXMAX + b * 8 + j]);
        float g = (mx - mean[c]) * rstd[c];
        float t = tanhf(g);
        float q1 = 2.0f * t;
        float q2 = 3.75f * t * t - 0.75f;
        float q3 = 1.8666666666666667f * t * q2 - 0.8f * q1;
        feat[c * 4 + 0] = 1.0f;
        feat[c * 4 + 1] = q1;
        feat[c * 4 + 2] = q2;
        feat[c * 4 + 3] = q3;
    }
    __syncthreads();
    const int o = blockIdx.x * 256 + threadIdx.x;
    float s = 0.f;
    for (int c = 0; c < 1024; c++) {
        float4 w4 = *(const float4*)(W6 + ((size_t)(64 + c) * 512 + o) * 4);
        s += feat[c * 4 + 0] * w4.x + feat[c * 4 + 1] * w4.y +
             feat[c * 4 + 2] * w4.z + feat[c * 4 + 3] * w4.w;
    }
    bias6[b * 512 + o] = s;
}

// ===================== host =====================
static const LayerP h_L[10] = {
    {  2,   64,   48,  128,       0,    0},
    { 64,   64,  192,  128,    6144,  128},
    { 64,   64,  192,  128,   30720,  256},
    { 64,  128,  192,  128,   55296,  384},
    {128, 1024,  384, 1024,   79872,  512},
    { 64,  512,  192,  512,  473088, 1536},
    {512,  256, 1536,  256,  571392, 2048},
    {256,  128,  768,  128,  964608, 2304},
    {128,  128,  384,  128, 1062912, 2432},
    {128,    3,  384,  128, 1112064, 2560},
};

static constexpr int SMEM_TILE = 196608;

extern "C" void kernel_launch(void* const* d_in, const int* in_sizes, int n_in,
                              void* d_out, int out_size)
{
    (void)in_sizes; (void)n_in; (void)out_size;
    const float* x = (const float*)d_in[0];
    WPtrs wp;
    for (int i = 0; i < 10; i++) wp.p[i] = (const float*)d_in[1 + i];

    float* buf = nullptr;
    cudaGetSymbolAddress((void**)&buf, g_buf);
    __nv_bfloat16* whi = nullptr;
    __nv_bfloat16* wlo = nullptr;
    cudaGetSymbolAddress((void**)&whi, g_whi);
    cudaGetSymbolAddress((void**)&wlo, g_wlo);

    float* h1 = buf + OFF_H1;
    float* h2 = buf + OFF_H2;
    float* h3 = buf + OFF_H3;
    float* h4 = buf + OFF_H4;
    float* h6 = buf + OFF_H6;
    float* h7 = buf + OFF_H7;
    float* h8 = buf + OFF_H8;
    float* h9 = buf + OFF_H9;
    float* meanB = buf + OFF_MEAN;
    float* rstdB = buf + OFF_RSTD;
    float* bias6 = buf + OFF_B6;
    float* cbB   = buf + OFF_CB;
    float* ps    = buf + OFF_PS;
    float* pqb   = buf + OFF_PQ;
    float* pm    = buf + OFF_PM;

    cudaFuncSetAttribute(kan_mma<4, 4, 128>,
                         cudaFuncAttributeMaxDynamicSharedMemorySize, SMEM_TILE);
    cudaFuncSetAttribute(kan_mma<2, 8, 256>,
                         cudaFuncAttributeMaxDynamicSharedMemorySize, SMEM_TILE);

    {
        dim3 g(1536, 8);
        wcvt_all<<<g, 256>>>(wp, whi, wlo);
    }
    {
        dim3 g(4, 8);
        cbias_all<<<g, 256>>>(wp, cbB);
    }

    auto M = [&](int s) { return meanB + s * 1024; };
    auto R = [&](int s) { return rstdB + s * 1024; };

    auto gbig = [&](int l, const float* Hin, const float* mn, const float* rs,
                    const float* bb, float* Hout, int wm, int st, int mx) {
        dim3 grid(BN_TOT / 128, h_L[l].rows / 256, 1);
        kan_mma<4, 4, 128><<<grid, 512, SMEM_TILE>>>(Hin, mn, rs,
            whi + h_L[l].woff, wlo + h_L[l].woff, cbB + h_L[l].cboff, bb,
            Hout, ps, pqb, pm,
            h_L[l].cin, h_L[l].cout, h_L[l].kp3, h_L[l].kp3 / 48, wm, st, mx);
    };
    auto gsm = [&](int l, const float* Hin, const float* mn, const float* rs,
                   const float* bb, float* Hout, int wm, int st, int mx) {
        dim3 grid(BN_TOT / 256, h_L[l].rows / 128, 1);
        kan_mma<2, 8, 256><<<grid, 512, SMEM_TILE>>>(Hin, mn, rs,
            whi + h_L[l].woff, wlo + h_L[l].woff, cbB + h_L[l].cboff, bb,
            Hout, ps, pqb, pm,
            h_L[l].cin, h_L[l].cout, h_L[l].kp3, h_L[l].kp3 / 48, wm, st, mx);
    };
    auto fin = [&](int slot, int C, int gx) {
        bn_fin<<<(C + 7) / 8, 256>>>(ps, pqb, M(slot), R(slot), C, gx);
    };

    // L1: exact scalar fp32
    layer1_scalar<<<BN_TOT / 256, 256>>>(x, wp.p[0], h1);
    bn_stats_direct<<<64, 256>>>(h1, M(0), R(0));

    gsm(1, h1, M(0), R(0), nullptr, h2, 0, 1, 0);        fin(1, 64, 128);
    gsm(2, h2, M(1), R(1), nullptr, h3, 0, 1, 0);        fin(2, 64, 128);
    gsm(3, h3, M(2), R(2), nullptr, h4, 0, 1, 0);        fin(3, 128, 128);
    gbig(4, h4, M(3), R(3), nullptr, nullptr, 2, 1, 1);  fin(4, 1024, 256);

    {
        dim3 g(2, BB);
        gfbias6<<<g, 256>>>(pm, M(4), R(4), wp.p[5], bias6);
    }

    gbig(5, h2, M(1), R(1), bias6, h6, 0, 1, 0);         fin(5, 512, 256);
    gbig(6, h6, M(5), R(5), nullptr, h7, 0, 1, 0);       fin(6, 256, 256);
    gsm(7, h7, M(6), R(6), nullptr, h8, 0, 1, 0);        fin(7, 128, 128);
    gsm(8, h8, M(7), R(7), nullptr, h9, 0, 1, 0);        fin(8, 128, 128);

    // L10: exact scalar fp32 straight to d_out
    layer10_scalar<<<BN_TOT / 256, 256>>>(h9, M(8), R(8), wp.p[9], (float*)d_out);
}